// round 13
// baseline (speedup 1.0000x reference)
#include <cuda_runtime.h>
#include <cuda_fp16.h>
#include <math.h>

#define DIMC 1536
#define NHEADS 12
#define HD 128
#define MAX_ATTN_W 5632
#define MAXS 3200
#define PADW 5632

__device__ __half g_qraw[MAXS * DIMC];          // GEMM q output (half, pre-norm)
__device__ __half g_kraw[MAXS * DIMC];          // GEMM k output (half, pre-norm)
__device__ __half g_qh[MAXS * DIMC];            // normed+roped+scaled q
__device__ __half g_oh[MAXS * DIMC];
__device__ __half g_wh[4 * DIMC * DIMC];
__device__ __half g_xh[MAXS * DIMC];
__device__ __half g_kw[NHEADS * PADW * HD];     // K window [h][key][d]
__device__ __half g_vw[NHEADS * PADW * HD];     // V window [h][key][d]

__device__ __forceinline__ unsigned pk2(float a, float b) {
    __half2 h = __floats2half2_rn(a, b);
    return *(unsigned*)&h;
}

__device__ __forceinline__ void mma_f16(float* d, const unsigned* a,
                                        unsigned b0, unsigned b1) {
    asm volatile(
        "mma.sync.aligned.m16n8k16.row.col.f32.f16.f16.f32 "
        "{%0,%1,%2,%3}, {%4,%5,%6,%7}, {%8,%9}, {%0,%1,%2,%3};\n"
        : "+f"(d[0]), "+f"(d[1]), "+f"(d[2]), "+f"(d[3])
        : "r"(a[0]), "r"(a[1]), "r"(a[2]), "r"(a[3]), "r"(b0), "r"(b1));
}

__device__ __forceinline__ void ldsm4(unsigned& r0, unsigned& r1,
                                      unsigned& r2, unsigned& r3, unsigned a) {
    asm volatile("ldmatrix.sync.aligned.m8n8.x4.shared.b16 {%0,%1,%2,%3}, [%4];"
                 : "=r"(r0), "=r"(r1), "=r"(r2), "=r"(r3) : "r"(a));
}
__device__ __forceinline__ void ldsm4t(unsigned& r0, unsigned& r1,
                                       unsigned& r2, unsigned& r3, unsigned a) {
    asm volatile("ldmatrix.sync.aligned.m8n8.x4.trans.shared.b16 {%0,%1,%2,%3}, [%4];"
                 : "=r"(r0), "=r"(r1), "=r"(r2), "=r"(r3) : "r"(a));
}

__device__ __forceinline__ unsigned s2u(const void* p) {
    return (unsigned)__cvta_generic_to_shared(p);
}

__device__ __forceinline__ void cpa16(void* dst_smem, const void* src) {
    unsigned d = (unsigned)__cvta_generic_to_shared(dst_smem);
    asm volatile("cp.async.cg.shared.global [%0], [%1], 16;\n" :: "r"(d), "l"(src));
}
#define CP_COMMIT() asm volatile("cp.async.commit_group;\n" ::: "memory")

// ---------------------------------------------------------------------------
__global__ __launch_bounds__(256) void prep_half_kernel(
    const float* __restrict__ s0, const float* __restrict__ s1,
    const float* __restrict__ s2, const float* __restrict__ s3,
    __half* __restrict__ dst, int n8_each)
{
    int i = blockIdx.x * 256 + threadIdx.x;
    int total = (s1 ? 4 : 1) * n8_each;
    if (i >= total) return;
    int wsel = i / n8_each, r = i - wsel * n8_each;
    const float* src = (wsel == 0) ? s0 : (wsel == 1) ? s1 : (wsel == 2) ? s2 : s3;
    float4 v0 = ((const float4*)src)[2 * r];
    float4 v1 = ((const float4*)src)[2 * r + 1];
    uint4 o;
    o.x = pk2(v0.x, v0.y); o.y = pk2(v0.z, v0.w);
    o.z = pk2(v1.x, v1.y); o.w = pk2(v1.z, v1.w);
    ((uint4*)dst)[i] = o;
}

// ---------------------------------------------------------------------------
// prep KV: cache rows -> g_kw/g_vw; zero-pad j >= L. Fresh K from norm_rope,
// fresh V from GEMM z=2. grid (88, NHEADS), 256 threads.
// ---------------------------------------------------------------------------
__global__ __launch_bounds__(256) void prep_kv_kernel(
    const float* __restrict__ cache_k, const float* __restrict__ cache_v, int S,
    const int* __restrict__ p_cs, const int* __restrict__ p_ge,
    const int* __restrict__ p_le)
{
    int cs = *p_cs, ge = *p_ge, le = *p_le;
    int local_end = le + cs + S - ge;
    int win_start = local_end - MAX_ATTN_W;
    if (win_start < 0) win_start = 0;
    int L = local_end - win_start;
    int Lc = L - S;

    int h = blockIdx.y;
    int j0 = blockIdx.x * 64;
    int tid = threadIdx.x;

#pragma unroll
    for (int i = 0; i < 8; i++) {
        int idx = tid + i * 256;
        int key = idx >> 5, c4 = idx & 31;
        int j = j0 + key;
        size_t wo = ((size_t)h * PADW + j) * HD + c4 * 4;
        if (j < Lc) {
            int jg = win_start + j;
            size_t co = ((size_t)jg * NHEADS + h) * HD + c4 * 4;
            float4 kv = *(const float4*)(cache_k + co);
            float4 vv = *(const float4*)(cache_v + co);
            uint2 ko; ko.x = pk2(kv.x, kv.y); ko.y = pk2(kv.z, kv.w);
            uint2 vo; vo.x = pk2(vv.x, vv.y); vo.y = pk2(vv.z, vv.w);
            *(uint2*)(g_kw + wo) = ko;
            *(uint2*)(g_vw + wo) = vo;
        } else if (j >= L) {
            uint2 zz; zz.x = 0u; zz.y = 0u;
            *(uint2*)(g_kw + wo) = zz;
            *(uint2*)(g_vw + wo) = zz;
        }
    }
}

// ---------------------------------------------------------------------------
// GEMM fp16 + ldmatrix. BM=64, BN=128, BK=32, 128 thr.
// vmode=1: z=0 -> half Hq, z=1 -> half Hk, z=2 -> half into g_vw window.
// vmode=0: fp32 out to Cf.
// ---------------------------------------------------------------------------
__global__ __launch_bounds__(128) void gemm_f16_kernel(
    const __half* __restrict__ A, const __half* __restrict__ Wbase,
    const float* __restrict__ b0p, const float* __restrict__ b1p,
    const float* __restrict__ b2p, float* __restrict__ Cf,
    __half* __restrict__ Hq, __half* __restrict__ Hk, int M, int vmode,
    const int* __restrict__ p_cs, const int* __restrict__ p_ge,
    const int* __restrict__ p_le)
{
    extern __shared__ float smf[];
    __half* sh = (__half*)smf;
    int z = blockIdx.z;
    const __half* W = Wbase + (size_t)z * DIMC * DIMC;
    const float* bias = (z == 0) ? b0p : (z == 1) ? b1p : b2p;

    int tid = threadIdx.x, warp = tid >> 5, lane = tid & 31;
    int g = lane >> 2, t = lane & 3;
    int wm = warp * 16;
    int bm = blockIdx.x * 64, bn = blockIdx.y * 128;

    int lr = lane & 7;
    int prB = (((lane >> 3) & 2) << 2) + lr;
    int pcB = ((lane >> 3) & 1) * 8;
    int prA = (((lane >> 3) & 1) << 3) + lr;
    int pcA = ((lane >> 4) & 1) * 8;

    float acc[16][4];
#pragma unroll
    for (int nt = 0; nt < 16; nt++)
#pragma unroll
        for (int i = 0; i < 4; i++) acc[nt][i] = 0.0f;

#define GF(stg, kt)                                                           \
    {                                                                         \
        __half* As_ = sh + (stg) * 7680;                                      \
        __half* Bs_ = As_ + 2560;                                             \
        const __half* Ag_ = A + (size_t)bm * DIMC + (kt) * 32;                \
        const __half* Wg_ = W + (size_t)bn * DIMC + (kt) * 32;                \
        _Pragma("unroll")                                                     \
        for (int j = 0; j < 2; j++) {                                         \
            int idx = tid + j * 128;                                          \
            int row = idx >> 2, c = idx & 3;                                  \
            cpa16(As_ + row * 40 + c * 8, Ag_ + (size_t)row * DIMC + c * 8);  \
        }                                                                     \
        _Pragma("unroll")                                                     \
        for (int j = 0; j < 4; j++) {                                         \
            int idx = tid + j * 128;                                          \
            int row = idx >> 2, c = idx & 3;                                  \
            cpa16(Bs_ + row * 40 + c * 8, Wg_ + (size_t)row * DIMC + c * 8);  \
        }                                                                     \
    }

    GF(0, 0); CP_COMMIT();
    for (int kt = 0; kt < 48; kt++) {
        int s = kt & 1;
        if (kt + 1 < 48) {
            GF(s ^ 1, kt + 1); CP_COMMIT();
            asm volatile("cp.async.wait_group 1;\n" ::: "memory");
        } else {
            asm volatile("cp.async.wait_group 0;\n" ::: "memory");
        }
        __syncthreads();
        const __half* As = sh + s * 7680;
        const __half* Bs = As + 2560;
        unsigned abase = s2u(As) + ((wm + prA) * 40 + pcA) * 2;
        unsigned bbase = s2u(Bs) + (prB * 40 + pcB) * 2;
#pragma unroll
        for (int kst = 0; kst < 2; kst++) {
            unsigned af[4];
            ldsm4(af[0], af[1], af[2], af[3], abase + kst * 32);
#pragma unroll
            for (int np = 0; np < 8; np++) {
                unsigned b0, b1, b2, b3;
                ldsm4(b0, b1, b2, b3, bbase + (np * 16 * 40) * 2 + kst * 32);
                mma_f16(acc[np * 2], af, b0, b1);
                mma_f16(acc[np * 2 + 1], af, b2, b3);
            }
        }
        __syncthreads();
    }

    int m0 = bm + wm + g, m1 = m0 + 8;
    bool vpath = (vmode != 0) && (z == 2);
    int Loff = 0, h = 0;
    if (vpath) {
        int cs = *p_cs, ge = *p_ge, le = *p_le;
        int local_end = le + cs + M - ge;
        int win_start = local_end - MAX_ATTN_W;
        if (win_start < 0) win_start = 0;
        Loff = (local_end - win_start) - M;   // L - S
        h = blockIdx.y;                        // BN==HD: tile == head
    }
#pragma unroll
    for (int nt = 0; nt < 16; nt++) {
        int n = bn + nt * 8 + 2 * t;
        float bb0 = bias[n], bb1 = bias[n + 1];
        if (vmode == 0) {
            if (m0 < M)
                *(float2*)(Cf + (size_t)m0 * DIMC + n) =
                    make_float2(acc[nt][0] + bb0, acc[nt][1] + bb1);
            if (m1 < M)
                *(float2*)(Cf + (size_t)m1 * DIMC + n) =
                    make_float2(acc[nt][2] + bb0, acc[nt][3] + bb1);
        } else if (!vpath) {
            __half* H = (z == 0) ? Hq : Hk;
            if (m0 < M)
                *(unsigned*)(H + (size_t)m0 * DIMC + n) =
                    pk2(acc[nt][0] + bb0, acc[nt][1] + bb1);
            if (m1 < M)
                *(unsigned*)(H + (size_t)m1 * DIMC + n) =
                    pk2(acc[nt][2] + bb0, acc[nt][3] + bb1);
        } else {
            int d = nt * 8 + 2 * t;
            int j0w = m0 + Loff, j1w = m1 + Loff;
            if (m0 < M && j0w >= 0 && j0w < PADW)
                *(unsigned*)(g_vw + ((size_t)h * PADW + j0w) * HD + d) =
                    pk2(acc[nt][0] + bb0, acc[nt][1] + bb1);
            if (m1 < M && j1w >= 0 && j1w < PADW)
                *(unsigned*)(g_vw + ((size_t)h * PADW + j1w) * HD + d) =
                    pk2(acc[nt][2] + bb0, acc[nt][3] + bb1);
        }
    }
}

// ---------------------------------------------------------------------------
// RMSNorm (fp32 math on half input) + RoPE.
// q -> g_qh (half, pre-scaled); k -> g_kw window slot (half).
// ---------------------------------------------------------------------------
__global__ __launch_bounds__(256) void norm_rope_kernel(
    const __half* __restrict__ qb, const __half* __restrict__ kb,
    __half* __restrict__ qh,
    const float* __restrict__ gq, const float* __restrict__ gk,
    const float* __restrict__ theta, int S,
    const int* __restrict__ p_gh, const int* __restrict__ p_gw,
    const int* __restrict__ p_cs, const int* __restrict__ p_ge,
    const int* __restrict__ p_le)
{
    __shared__ float row[DIMC];
    __shared__ float red[256];

    int srow = blockIdx.x;
    int which = blockIdx.y;
    const __half* buf = which ? kb : qb;
    const float* g = which ? gk : gq;
    const unsigned* rptr = (const unsigned*)(buf + (size_t)srow * DIMC);

    int tid = threadIdx.x;
    float va[3], vb[3];
    float ss = 0.0f;
#pragma unroll
    for (int q = 0; q < 3; q++) {
        unsigned u = rptr[tid + q * 256];
        __half2 h2 = *(__half2*)&u;
        float a = __low2float(h2), b = __high2float(h2);
        va[q] = a; vb[q] = b;
        ss += a * a + b * b;
    }
    red[tid] = ss;
    __syncthreads();
    for (int o = 128; o > 0; o >>= 1) {
        if (tid < o) red[tid] += red[tid + o];
        __syncthreads();
    }
    float scale = rsqrtf(red[0] * (1.0f / DIMC) + 1e-6f);
#pragma unroll
    for (int q = 0; q < 3; q++) {
        int d = 2 * (tid + q * 256);
        row[d]     = va[q] * scale * g[d];
        row[d + 1] = vb[q] * scale * g[d + 1];
    }
    __syncthreads();

    int gh = *p_gh, gw = *p_gw, cs = *p_cs, ge = *p_ge, le = *p_le;
    int fs = gh * gw;
    int sf = cs / fs;
    int f = srow / fs;
    int rem = srow - f * fs;
    int hs = rem / gw;
    int ws = rem - hs * gw;

    int local_end = le + cs + S - ge;
    int win_start = local_end - MAX_ATTN_W;
    if (win_start < 0) win_start = 0;
    int L = local_end - win_start;
    int jw = srow + (L - S);

    const float qscale = 0.08838834764831845f;

    for (int p = tid; p < NHEADS * (HD / 2); p += 256) {
        int head = p >> 6;
        int i = p & 63;
        int trow = (i < 22) ? (sf + f) : ((i < 43) ? hs : ws);
        float ang = theta[trow * (HD / 2) + i];
        float sn, cn;
        __sincosf(ang, &sn, &cn);
        int d0 = head * HD + 2 * i;
        float xr = row[d0], xi = row[d0 + 1];
        float orr = xr * cn - xi * sn;
        float oii = xr * sn + xi * cn;
        if (which == 0) {
            *(unsigned*)(qh + (size_t)srow * DIMC + d0) =
                pk2(orr * qscale, oii * qscale);
        } else if (jw >= 0 && jw < PADW) {
            *(unsigned*)(g_kw + ((size_t)head * PADW + jw) * HD + 2 * i) =
                pk2(orr, oii);
        }
    }
}

// ---------------------------------------------------------------------------
// Flash fp16 + ldmatrix; V frags via ldmatrix.trans from [key][d] tiles.
// ---------------------------------------------------------------------------
__global__ __launch_bounds__(128) void flash_f16_kernel(
    const __half* __restrict__ qh, __half* __restrict__ obuf, int S,
    const int* __restrict__ p_cs, const int* __restrict__ p_ge,
    const int* __restrict__ p_le)
{
    extern __shared__ float smf[];
    __half* sh = (__half*)smf;
    __half* Ps = sh + 34816;

    int cs = *p_cs, ge = *p_ge, le = *p_le;
    int local_end = le + cs + S - ge;
    int win_start = local_end - MAX_ATTN_W;
    if (win_start < 0) win_start = 0;
    int L = local_end - win_start;

    int hh = blockIdx.y;
    int qbase = blockIdx.x * 64;
    int tid = threadIdx.x, warp = tid >> 5, lane = tid & 31;
    int g = lane >> 2, t = lane & 3;

    int lr = lane & 7;
    int prB = (((lane >> 3) & 2) << 2) + lr;
    int pcB = ((lane >> 3) & 1) * 8;
    int prA = (((lane >> 3) & 1) << 3) + lr;
    int pcA = ((lane >> 4) & 1) * 8;
    int vrow = ((lane >> 3) & 1) * 8 + lr;
    int vcol = ((lane >> 4) & 1) * 8;

    unsigned qa[8][4];
    {
        int r0 = qbase + warp * 16 + g, r1 = r0 + 8;
        const __half* q0p = qh + (size_t)r0 * DIMC + hh * HD;
        const __half* q1p = qh + (size_t)r1 * DIMC + hh * HD;
        bool v0 = r0 < S, v1 = r1 < S;
#pragma unroll
        for (int ks = 0; ks < 8; ks++) {
            int c = ks * 16 + 2 * t;
            qa[ks][0] = v0 ? *(const unsigned*)(q0p + c) : 0u;
            qa[ks][1] = v1 ? *(const unsigned*)(q1p + c) : 0u;
            qa[ks][2] = v0 ? *(const unsigned*)(q0p + c + 8) : 0u;
            qa[ks][3] = v1 ? *(const unsigned*)(q1p + c + 8) : 0u;
        }
    }

    float oacc[16][4];
#pragma unroll
    for (int nt = 0; nt < 16; nt++)
#pragma unroll
        for (int i = 0; i < 4; i++) oacc[nt][i] = 0.0f;
    float m0s = -1e30f, m1s = -1e30f, l0s = 0.0f, l1s = 0.0f;

    int prow0 = (warp * 16 + g) * 72, prow1 = prow0 + 8 * 72;
    unsigned pabase = s2u(Ps) + ((warp * 16 + prA) * 72 + pcA) * 2;
    int nkt = (L + 63) >> 6;

    const __half* kwb = g_kw + (size_t)hh * PADW * HD;
    const __half* vwb = g_vw + (size_t)hh * PADW * HD;

#define KVF(stg, kt)                                                          \
    {                                                                         \
        __half* Ks_ = sh + (stg) * 17408;                                     \
        __half* Vs_ = Ks_ + 8704;                                             \
        const __half* kb_ = kwb + (size_t)(kt) * 64 * HD;                     \
        const __half* vb_ = vwb + (size_t)(kt) * 64 * HD;                     \
        _Pragma("unroll")                                                     \
        for (int j = 0; j < 8; j++) {                                         \
            int idx = tid + j * 128;                                          \
            int row = idx >> 4, c = idx & 15;                                 \
            cpa16(Ks_ + row * 136 + c * 8, kb_ + (size_t)row * HD + c * 8);   \
            cpa16(Vs_ + row * 136 + c * 8, vb_ + (size_t)row * HD + c * 8);   \
        }                                                                     \
    }

    KVF(0, 0); CP_COMMIT();
    for (int kt = 0; kt < nkt; kt++) {
        int s = kt & 1;
        if (kt + 1 < nkt) {
            KVF(s ^ 1, kt + 1); CP_COMMIT();
            asm volatile("cp.async.wait_group 1;\n" ::: "memory");
        } else {
            asm volatile("cp.async.wait_group 0;\n" ::: "memory");
        }
        __syncthreads();
        const __half* Ks = sh + s * 17408;
        const __half* Vt = Ks + 8704;
        unsigned kbase = s2u(Ks) + (prB * 136 + pcB) * 2;
        unsigned vbase = s2u(Vt) + (vrow * 136 + vcol) * 2;

        float sacc[8][4];
#pragma unroll
        for (int nt = 0; nt < 8; nt++)
#pragma unroll
            for (int i = 0; i < 4; i++) sacc[nt][i] = 0.0f;
#pragma unroll
        for (int ks = 0; ks < 8; ks++) {
#pragma unroll
            for (int np = 0; np < 4; np++) {
                unsigned b0, b1, b2, b3;
                ldsm4(b0, b1, b2, b3, kbase + (np * 16 * 136) * 2 + ks * 32);
                mma_f16(sacc[np * 2], qa[ks], b0, b1);
                mma_f16(sacc[np * 2 + 1], qa[ks], b2, b3);
            }
        }

        int colb = kt * 64 + 2 * t;
        float rmax0 = -1e30f, rmax1 = -1e30f;
#pragma unroll
        for (int nt = 0; nt < 8; nt++) {
            int c = colb + nt * 8;
            if (c >= L)     { sacc[nt][0] = -1e30f; sacc[nt][2] = -1e30f; }
            if (c + 1 >= L) { sacc[nt][1] = -1e30f; sacc[nt][3] = -1e30f; }
            rmax0 = fmaxf(rmax0, fmaxf(sacc[nt][0], sacc[nt][1]));
            rmax1 = fmaxf(rmax1, fmaxf(sacc[nt][2], sacc[nt][3]));
        }
        rmax0 = fmaxf(rmax0, __shfl_xor_sync(0xffffffffu, rmax0, 1));
        rmax0 = fmaxf(rmax0, __shfl_xor_sync(0xffffffffu, rmax0, 2));
        rmax1 = fmaxf(rmax1, __shfl_xor_sync(0xffffffffu, rmax1, 1));
        rmax1 = fmaxf(rmax1, __shfl_xor_sync(0xffffffffu, rmax1, 2));
        float newm0 = fmaxf(m0s, rmax0), newm1 = fmaxf(m1s, rmax1);
        float fac0 = __expf(m0s - newm0), fac1 = __expf(m1s - newm1);
        m0s = newm0; m1s = newm1;

        float rs0 = 0.0f, rs1 = 0.0f;
#pragma unroll
        for (int nt = 0; nt < 8; nt++) {
            float p0 = __expf(sacc[nt][0] - newm0);
            float p1 = __expf(sacc[nt][1] - newm0);
            float p2 = __expf(sacc[nt][2] - newm1);
            float p3 = __expf(sacc[nt][3] - newm1);
            rs0 += p0 + p1; rs1 += p2 + p3;
            int cn = nt * 8 + 2 * t;
            *(unsigned*)(Ps + prow0 + cn) = pk2(p0, p1);
            *(unsigned*)(Ps + prow1 + cn) = pk2(p2, p3);
        }
        rs0 += __shfl_xor_sync(0xffffffffu, rs0, 1);
        rs0 += __shfl_xor_sync(0xffffffffu, rs0, 2);
        rs1 += __shfl_xor_sync(0xffffffffu, rs1, 1);
        rs1 += __shfl_xor_sync(0xffffffffu, rs1, 2);
        l0s = l0s * fac0 + rs0;
        l1s = l1s * fac1 + rs1;
#pragma unroll
        for (int nt = 0; nt < 16; nt++) {
            oacc[nt][0] *= fac0; oacc[nt][1] *= fac0;
            oacc[nt][2] *= fac1; oacc[nt][3] *= fac1;
        }
        __syncwarp();

#pragma unroll
        for (int kk = 0; kk < 4; kk++) {
            unsigned pa[4];
            ldsm4(pa[0], pa[1], pa[2], pa[3], pabase + kk * 32);
#pragma unroll
            for (int np = 0; np < 8; np++) {
                unsigned b0, b1, b2, b3;
                ldsm4t(b0, b1, b2, b3, vbase + kk * 16 * 136 * 2 + np * 32);
                mma_f16(oacc[np * 2], pa, b0, b1);
                mma_f16(oacc[np * 2 + 1], pa, b2, b3);
            }
        }
        __syncthreads();
    }

    float inv0 = 1.0f / l0s, inv1 = 1.0f / l1s;
    int r0 = qbase + warp * 16 + g, r1 = r0 + 8;
#pragma unroll
    for (int nt = 0; nt < 16; nt++) {
        int d = hh * HD + nt * 8 + 2 * t;
        if (r0 < S)
            *(unsigned*)(obuf + (size_t)r0 * DIMC + d) =
                pk2(oacc[nt][0] * inv0, oacc[nt][1] * inv0);
        if (r1 < S)
            *(unsigned*)(obuf + (size_t)r1 * DIMC + d) =
                pk2(oacc[nt][2] * inv1, oacc[nt][3] * inv1);
    }
}

// ---------------------------------------------------------------------------
extern "C" void kernel_launch(void* const* d_in, const int* in_sizes, int n_in,
                              void* d_out, int out_size)
{
    const float* x   = (const float*)d_in[0];
    const float* th  = (const float*)d_in[1];
    const float* ck  = (const float*)d_in[2];
    const float* cv  = (const float*)d_in[3];
    const float* wq  = (const float*)d_in[4];
    const float* bq  = (const float*)d_in[5];
    const float* wk  = (const float*)d_in[6];
    const float* bk  = (const float*)d_in[7];
    const float* wv  = (const float*)d_in[8];
    const float* bv  = (const float*)d_in[9];
    const float* wo  = (const float*)d_in[10];
    const float* bo  = (const float*)d_in[11];
    const float* gq  = (const float*)d_in[12];
    const float* gk  = (const float*)d_in[13];
    const int* p_gh  = (const int*)d_in[15];
    const int* p_gw  = (const int*)d_in[16];
    const int* p_cs  = (const int*)d_in[17];
    const int* p_ge  = (const int*)d_in[18];
    const int* p_le  = (const int*)d_in[19];
    float* out = (float*)d_out;

    int S = in_sizes[0] / DIMC;

    __half *xhp, *ohp, *whp, *qhp, *qrp, *krp;
    cudaGetSymbolAddress((void**)&xhp, g_xh);
    cudaGetSymbolAddress((void**)&ohp, g_oh);
    cudaGetSymbolAddress((void**)&whp, g_wh);
    cudaGetSymbolAddress((void**)&qhp, g_qh);
    cudaGetSymbolAddress((void**)&qrp, g_qraw);
    cudaGetSymbolAddress((void**)&krp, g_kraw);

    int wn8 = DIMC * DIMC / 8;
    prep_half_kernel<<<(4 * wn8 + 255) / 256, 256>>>(wq, wk, wv, wo, whp, wn8);
    int xn8 = S * DIMC / 8;
    prep_half_kernel<<<(xn8 + 255) / 256, 256>>>(x, 0, 0, 0, xhp, xn8);

    size_t gsm = 30720;
    cudaFuncSetAttribute(gemm_f16_kernel, cudaFuncAttributeMaxDynamicSharedMemorySize,
                         (int)gsm);
    dim3 gqkv((S + 63) / 64, DIMC / 128, 3);
    gemm_f16_kernel<<<gqkv, 128, gsm>>>(xhp, whp, bq, bk, bv, out, qrp, krp, S, 1,
                                        p_cs, p_ge, p_le);

    norm_rope_kernel<<<dim3(S, 2), 256>>>(qrp, krp, qhp, gq, gk, th, S,
                                          p_gh, p_gw, p_cs, p_ge, p_le);

    prep_kv_kernel<<<dim3(PADW / 64, NHEADS), 256>>>(ck, cv, S, p_cs, p_ge, p_le);

    size_t fsm = (size_t)(34816 + 64 * 72) * sizeof(__half);
    cudaFuncSetAttribute(flash_f16_kernel, cudaFuncAttributeMaxDynamicSharedMemorySize,
                         (int)fsm);
    flash_f16_kernel<<<dim3((S + 63) / 64, NHEADS), 128, fsm>>>(
        qhp, ohp, S, p_cs, p_ge, p_le);

    dim3 go((S + 63) / 64, DIMC / 128, 1);
    gemm_f16_kernel<<<go, 128, gsm>>>(ohp, whp + (size_t)3 * DIMC * DIMC,
                                      bo, bo, bo, out, qrp, krp, S, 0,
                                      p_cs, p_ge, p_le);
}

// round 14
// speedup vs baseline: 1.5747x; 1.5747x over previous
#include <cuda_runtime.h>
#include <cuda_fp16.h>
#include <math.h>

#define DIMC 1536
#define NHEADS 12
#define HD 128
#define MAX_ATTN_W 5632
#define MAXS 3200
#define PADW 5632

__device__ float  g_q[MAXS * DIMC];
__device__ float  g_k[MAXS * DIMC];
__device__ __half g_qh[MAXS * DIMC];
__device__ __half g_oh[MAXS * DIMC];
__device__ __half g_wh[4 * DIMC * DIMC];
__device__ __half g_xh[MAXS * DIMC];
__device__ __half g_kw[NHEADS * PADW * HD];     // K window [h][key][d]
__device__ __half g_vw[NHEADS * PADW * HD];     // V window [h][key][d]

__device__ __forceinline__ unsigned pk2(float a, float b) {
    __half2 h = __floats2half2_rn(a, b);
    return *(unsigned*)&h;
}

__device__ __forceinline__ void mma_f16(float* d, const unsigned* a,
                                        unsigned b0, unsigned b1) {
    asm volatile(
        "mma.sync.aligned.m16n8k16.row.col.f32.f16.f16.f32 "
        "{%0,%1,%2,%3}, {%4,%5,%6,%7}, {%8,%9}, {%0,%1,%2,%3};\n"
        : "+f"(d[0]), "+f"(d[1]), "+f"(d[2]), "+f"(d[3])
        : "r"(a[0]), "r"(a[1]), "r"(a[2]), "r"(a[3]), "r"(b0), "r"(b1));
}

__device__ __forceinline__ void ldsm4(unsigned& r0, unsigned& r1,
                                      unsigned& r2, unsigned& r3, unsigned a) {
    asm volatile("ldmatrix.sync.aligned.m8n8.x4.shared.b16 {%0,%1,%2,%3}, [%4];"
                 : "=r"(r0), "=r"(r1), "=r"(r2), "=r"(r3) : "r"(a));
}
__device__ __forceinline__ void ldsm4t(unsigned& r0, unsigned& r1,
                                       unsigned& r2, unsigned& r3, unsigned a) {
    asm volatile("ldmatrix.sync.aligned.m8n8.x4.trans.shared.b16 {%0,%1,%2,%3}, [%4];"
                 : "=r"(r0), "=r"(r1), "=r"(r2), "=r"(r3) : "r"(a));
}

__device__ __forceinline__ unsigned s2u(const void* p) {
    return (unsigned)__cvta_generic_to_shared(p);
}

__device__ __forceinline__ void cpa16(void* dst_smem, const void* src) {
    unsigned d = (unsigned)__cvta_generic_to_shared(dst_smem);
    asm volatile("cp.async.cg.shared.global [%0], [%1], 16;\n" :: "r"(d), "l"(src));
}
#define CP_COMMIT() asm volatile("cp.async.commit_group;\n" ::: "memory")

// ---------------------------------------------------------------------------
__global__ __launch_bounds__(256) void prep_half_kernel(
    const float* __restrict__ s0, const float* __restrict__ s1,
    const float* __restrict__ s2, const float* __restrict__ s3,
    __half* __restrict__ dst, int n8_each)
{
    int i = blockIdx.x * 256 + threadIdx.x;
    int total = (s1 ? 4 : 1) * n8_each;
    if (i >= total) return;
    int wsel = i / n8_each, r = i - wsel * n8_each;
    const float* src = (wsel == 0) ? s0 : (wsel == 1) ? s1 : (wsel == 2) ? s2 : s3;
    float4 v0 = ((const float4*)src)[2 * r];
    float4 v1 = ((const float4*)src)[2 * r + 1];
    uint4 o;
    o.x = pk2(v0.x, v0.y); o.y = pk2(v0.z, v0.w);
    o.z = pk2(v1.x, v1.y); o.w = pk2(v1.z, v1.w);
    ((uint4*)dst)[i] = o;
}

// ---------------------------------------------------------------------------
// prep KV: cache rows -> g_kw/g_vw; zero-pad j >= L. Fresh K from norm_rope,
// fresh V from GEMM z=2. grid (88, NHEADS), 256 threads.
// ---------------------------------------------------------------------------
__global__ __launch_bounds__(256) void prep_kv_kernel(
    const float* __restrict__ cache_k, const float* __restrict__ cache_v, int S,
    const int* __restrict__ p_cs, const int* __restrict__ p_ge,
    const int* __restrict__ p_le)
{
    int cs = *p_cs, ge = *p_ge, le = *p_le;
    int local_end = le + cs + S - ge;
    int win_start = local_end - MAX_ATTN_W;
    if (win_start < 0) win_start = 0;
    int L = local_end - win_start;
    int Lc = L - S;

    int h = blockIdx.y;
    int j0 = blockIdx.x * 64;
    int tid = threadIdx.x;

#pragma unroll
    for (int i = 0; i < 8; i++) {
        int idx = tid + i * 256;
        int key = idx >> 5, c4 = idx & 31;
        int j = j0 + key;
        size_t wo = ((size_t)h * PADW + j) * HD + c4 * 4;
        if (j < Lc) {
            int jg = win_start + j;
            size_t co = ((size_t)jg * NHEADS + h) * HD + c4 * 4;
            float4 kv = *(const float4*)(cache_k + co);
            float4 vv = *(const float4*)(cache_v + co);
            uint2 ko; ko.x = pk2(kv.x, kv.y); ko.y = pk2(kv.z, kv.w);
            uint2 vo; vo.x = pk2(vv.x, vv.y); vo.y = pk2(vv.z, vv.w);
            *(uint2*)(g_kw + wo) = ko;
            *(uint2*)(g_vw + wo) = vo;
        } else if (j >= L) {
            uint2 zz; zz.x = 0u; zz.y = 0u;
            *(uint2*)(g_kw + wo) = zz;
            *(uint2*)(g_vw + wo) = zz;
        }
    }
}

// ---------------------------------------------------------------------------
// GEMM fp16 + ldmatrix. BM=64, BN=128, BK=32, 128 thr.
// vmode=1 && z==2: V output written half into g_vw window slots.
// ---------------------------------------------------------------------------
__global__ __launch_bounds__(128) void gemm_f16_kernel(
    const __half* __restrict__ A, const __half* __restrict__ Wbase,
    const float* __restrict__ b0p, const float* __restrict__ b1p,
    const float* __restrict__ b2p, float* __restrict__ C0,
    float* __restrict__ C1, int M, int vmode,
    const int* __restrict__ p_cs, const int* __restrict__ p_ge,
    const int* __restrict__ p_le)
{
    extern __shared__ float smf[];
    __half* sh = (__half*)smf;
    int z = blockIdx.z;
    const __half* W = Wbase + (size_t)z * DIMC * DIMC;
    const float* bias = (z == 0) ? b0p : (z == 1) ? b1p : b2p;
    float* C = (z == 0) ? C0 : C1;

    int tid = threadIdx.x, warp = tid >> 5, lane = tid & 31;
    int g = lane >> 2, t = lane & 3;
    int wm = warp * 16;
    int bm = blockIdx.x * 64, bn = blockIdx.y * 128;

    int lr = lane & 7;
    int prB = (((lane >> 3) & 2) << 2) + lr;
    int pcB = ((lane >> 3) & 1) * 8;
    int prA = (((lane >> 3) & 1) << 3) + lr;
    int pcA = ((lane >> 4) & 1) * 8;

    float acc[16][4];
#pragma unroll
    for (int nt = 0; nt < 16; nt++)
#pragma unroll
        for (int i = 0; i < 4; i++) acc[nt][i] = 0.0f;

#define GF(stg, kt)                                                           \
    {                                                                         \
        __half* As_ = sh + (stg) * 7680;                                      \
        __half* Bs_ = As_ + 2560;                                             \
        const __half* Ag_ = A + (size_t)bm * DIMC + (kt) * 32;                \
        const __half* Wg_ = W + (size_t)bn * DIMC + (kt) * 32;                \
        _Pragma("unroll")                                                     \
        for (int j = 0; j < 2; j++) {                                         \
            int idx = tid + j * 128;                                          \
            int row = idx >> 2, c = idx & 3;                                  \
            cpa16(As_ + row * 40 + c * 8, Ag_ + (size_t)row * DIMC + c * 8);  \
        }                                                                     \
        _Pragma("unroll")                                                     \
        for (int j = 0; j < 4; j++) {                                         \
            int idx = tid + j * 128;                                          \
            int row = idx >> 2, c = idx & 3;                                  \
            cpa16(Bs_ + row * 40 + c * 8, Wg_ + (size_t)row * DIMC + c * 8);  \
        }                                                                     \
    }

    GF(0, 0); CP_COMMIT();
    for (int kt = 0; kt < 48; kt++) {
        int s = kt & 1;
        if (kt + 1 < 48) {
            GF(s ^ 1, kt + 1); CP_COMMIT();
            asm volatile("cp.async.wait_group 1;\n" ::: "memory");
        } else {
            asm volatile("cp.async.wait_group 0;\n" ::: "memory");
        }
        __syncthreads();
        const __half* As = sh + s * 7680;
        const __half* Bs = As + 2560;
        unsigned abase = s2u(As) + ((wm + prA) * 40 + pcA) * 2;
        unsigned bbase = s2u(Bs) + (prB * 40 + pcB) * 2;
#pragma unroll
        for (int kst = 0; kst < 2; kst++) {
            unsigned af[4];
            ldsm4(af[0], af[1], af[2], af[3], abase + kst * 32);
#pragma unroll
            for (int np = 0; np < 8; np++) {
                unsigned b0, b1, b2, b3;
                ldsm4(b0, b1, b2, b3, bbase + (np * 16 * 40) * 2 + kst * 32);
                mma_f16(acc[np * 2], af, b0, b1);
                mma_f16(acc[np * 2 + 1], af, b2, b3);
            }
        }
        __syncthreads();
    }

    int m0 = bm + wm + g, m1 = m0 + 8;
    bool vpath = (vmode != 0) && (z == 2);
    int Loff = 0, h = 0;
    if (vpath) {
        int cs = *p_cs, ge = *p_ge, le = *p_le;
        int local_end = le + cs + M - ge;
        int win_start = local_end - MAX_ATTN_W;
        if (win_start < 0) win_start = 0;
        Loff = (local_end - win_start) - M;   // L - S
        h = blockIdx.y;                        // BN==HD: tile == head
    }
#pragma unroll
    for (int nt = 0; nt < 16; nt++) {
        int n = bn + nt * 8 + 2 * t;
        float bb0 = bias[n], bb1 = bias[n + 1];
        if (!vpath) {
            if (m0 < M)
                *(float2*)(C + (size_t)m0 * DIMC + n) =
                    make_float2(acc[nt][0] + bb0, acc[nt][1] + bb1);
            if (m1 < M)
                *(float2*)(C + (size_t)m1 * DIMC + n) =
                    make_float2(acc[nt][2] + bb0, acc[nt][3] + bb1);
        } else {
            int d = nt * 8 + 2 * t;
            int j0w = m0 + Loff, j1w = m1 + Loff;
            if (m0 < M && j0w >= 0 && j0w < PADW)
                *(unsigned*)(g_vw + ((size_t)h * PADW + j0w) * HD + d) =
                    pk2(acc[nt][0] + bb0, acc[nt][1] + bb1);
            if (m1 < M && j1w >= 0 && j1w < PADW)
                *(unsigned*)(g_vw + ((size_t)h * PADW + j1w) * HD + d) =
                    pk2(acc[nt][2] + bb0, acc[nt][3] + bb1);
        }
    }
}

// ---------------------------------------------------------------------------
__global__ __launch_bounds__(256) void norm_rope_kernel(
    const float* __restrict__ qb, const float* __restrict__ kb,
    __half* __restrict__ qh,
    const float* __restrict__ gq, const float* __restrict__ gk,
    const float* __restrict__ theta, int S,
    const int* __restrict__ p_gh, const int* __restrict__ p_gw,
    const int* __restrict__ p_cs, const int* __restrict__ p_ge,
    const int* __restrict__ p_le)
{
    __shared__ float row[DIMC];
    __shared__ float red[256];

    int srow = blockIdx.x;
    int which = blockIdx.y;
    const float* buf = which ? kb : qb;
    const float* g = which ? gk : gq;
    const float* rptr = buf + (size_t)srow * DIMC;

    int tid = threadIdx.x;
    float vals[6];
    float ss = 0.0f;
#pragma unroll
    for (int q = 0; q < 6; q++) {
        int d = tid + q * 256;
        float v = rptr[d];
        vals[q] = v;
        ss += v * v;
    }
    red[tid] = ss;
    __syncthreads();
    for (int o = 128; o > 0; o >>= 1) {
        if (tid < o) red[tid] += red[tid + o];
        __syncthreads();
    }
    float scale = rsqrtf(red[0] * (1.0f / DIMC) + 1e-6f);
#pragma unroll
    for (int q = 0; q < 6; q++) {
        int d = tid + q * 256;
        row[d] = vals[q] * scale * g[d];
    }
    __syncthreads();

    int gh = *p_gh, gw = *p_gw, cs = *p_cs, ge = *p_ge, le = *p_le;
    int fs = gh * gw;
    int sf = cs / fs;
    int f = srow / fs;
    int rem = srow - f * fs;
    int hs = rem / gw;
    int ws = rem - hs * gw;

    int local_end = le + cs + S - ge;
    int win_start = local_end - MAX_ATTN_W;
    if (win_start < 0) win_start = 0;
    int L = local_end - win_start;
    int jw = srow + (L - S);

    const float qscale = 0.08838834764831845f;

    for (int p = tid; p < NHEADS * (HD / 2); p += 256) {
        int head = p >> 6;
        int i = p & 63;
        int trow = (i < 22) ? (sf + f) : ((i < 43) ? hs : ws);
        float ang = theta[trow * (HD / 2) + i];
        float sn, cn;
        __sincosf(ang, &sn, &cn);
        int d0 = head * HD + 2 * i;
        float xr = row[d0], xi = row[d0 + 1];
        float orr = xr * cn - xi * sn;
        float oii = xr * sn + xi * cn;
        if (which == 0) {
            *(unsigned*)(qh + (size_t)srow * DIMC + d0) =
                pk2(orr * qscale, oii * qscale);
        } else if (jw >= 0 && jw < PADW) {
            *(unsigned*)(g_kw + ((size_t)head * PADW + jw) * HD + 2 * i) =
                pk2(orr, oii);
        }
    }
}

// ---------------------------------------------------------------------------
// Flash fp16 + ldmatrix. P kept in REGISTERS (C-frag == A-frag layout for
// m16n8k16): no Ps smem, no syncwarp, no ldmatrix for P.
// ---------------------------------------------------------------------------
__global__ __launch_bounds__(128) void flash_f16_kernel(
    const __half* __restrict__ qh, __half* __restrict__ obuf, int S,
    const int* __restrict__ p_cs, const int* __restrict__ p_ge,
    const int* __restrict__ p_le)
{
    extern __shared__ float smf[];
    __half* sh = (__half*)smf;

    int cs = *p_cs, ge = *p_ge, le = *p_le;
    int local_end = le + cs + S - ge;
    int win_start = local_end - MAX_ATTN_W;
    if (win_start < 0) win_start = 0;
    int L = local_end - win_start;

    int hh = blockIdx.y;
    int qbase = blockIdx.x * 64;
    int tid = threadIdx.x, warp = tid >> 5, lane = tid & 31;
    int g = lane >> 2, t = lane & 3;

    int lr = lane & 7;
    int prB = (((lane >> 3) & 2) << 2) + lr;
    int pcB = ((lane >> 3) & 1) * 8;
    int vrow = ((lane >> 3) & 1) * 8 + lr;
    int vcol = ((lane >> 4) & 1) * 8;

    unsigned qa[8][4];
    {
        int r0 = qbase + warp * 16 + g, r1 = r0 + 8;
        const __half* q0p = qh + (size_t)r0 * DIMC + hh * HD;
        const __half* q1p = qh + (size_t)r1 * DIMC + hh * HD;
        bool v0 = r0 < S, v1 = r1 < S;
#pragma unroll
        for (int ks = 0; ks < 8; ks++) {
            int c = ks * 16 + 2 * t;
            qa[ks][0] = v0 ? *(const unsigned*)(q0p + c) : 0u;
            qa[ks][1] = v1 ? *(const unsigned*)(q1p + c) : 0u;
            qa[ks][2] = v0 ? *(const unsigned*)(q0p + c + 8) : 0u;
            qa[ks][3] = v1 ? *(const unsigned*)(q1p + c + 8) : 0u;
        }
    }

    float oacc[16][4];
#pragma unroll
    for (int nt = 0; nt < 16; nt++)
#pragma unroll
        for (int i = 0; i < 4; i++) oacc[nt][i] = 0.0f;
    float m0s = -1e30f, m1s = -1e30f, l0s = 0.0f, l1s = 0.0f;

    int nkt = (L + 63) >> 6;

    const __half* kwb = g_kw + (size_t)hh * PADW * HD;
    const __half* vwb = g_vw + (size_t)hh * PADW * HD;

#define KVF(stg, kt)                                                          \
    {                                                                         \
        __half* Ks_ = sh + (stg) * 17408;                                     \
        __half* Vs_ = Ks_ + 8704;                                             \
        const __half* kb_ = kwb + (size_t)(kt) * 64 * HD;                     \
        const __half* vb_ = vwb + (size_t)(kt) * 64 * HD;                     \
        _Pragma("unroll")                                                     \
        for (int j = 0; j < 8; j++) {                                         \
            int idx = tid + j * 128;                                          \
            int row = idx >> 4, c = idx & 15;                                 \
            cpa16(Ks_ + row * 136 + c * 8, kb_ + (size_t)row * HD + c * 8);   \
            cpa16(Vs_ + row * 136 + c * 8, vb_ + (size_t)row * HD + c * 8);   \
        }                                                                     \
    }

    KVF(0, 0); CP_COMMIT();
    for (int kt = 0; kt < nkt; kt++) {
        int s = kt & 1;
        if (kt + 1 < nkt) {
            KVF(s ^ 1, kt + 1); CP_COMMIT();
            asm volatile("cp.async.wait_group 1;\n" ::: "memory");
        } else {
            asm volatile("cp.async.wait_group 0;\n" ::: "memory");
        }
        __syncthreads();
        const __half* Ks = sh + s * 17408;
        const __half* Vt = Ks + 8704;
        unsigned kbase = s2u(Ks) + (prB * 136 + pcB) * 2;
        unsigned vbase = s2u(Vt) + (vrow * 136 + vcol) * 2;

        float sacc[8][4];
#pragma unroll
        for (int nt = 0; nt < 8; nt++)
#pragma unroll
            for (int i = 0; i < 4; i++) sacc[nt][i] = 0.0f;
#pragma unroll
        for (int ks = 0; ks < 8; ks++) {
#pragma unroll
            for (int np = 0; np < 4; np++) {
                unsigned b0, b1, b2, b3;
                ldsm4(b0, b1, b2, b3, kbase + (np * 16 * 136) * 2 + ks * 32);
                mma_f16(sacc[np * 2], qa[ks], b0, b1);
                mma_f16(sacc[np * 2 + 1], qa[ks], b2, b3);
            }
        }

        int colb = kt * 64 + 2 * t;
        float rmax0 = -1e30f, rmax1 = -1e30f;
#pragma unroll
        for (int nt = 0; nt < 8; nt++) {
            int c = colb + nt * 8;
            if (c >= L)     { sacc[nt][0] = -1e30f; sacc[nt][2] = -1e30f; }
            if (c + 1 >= L) { sacc[nt][1] = -1e30f; sacc[nt][3] = -1e30f; }
            rmax0 = fmaxf(rmax0, fmaxf(sacc[nt][0], sacc[nt][1]));
            rmax1 = fmaxf(rmax1, fmaxf(sacc[nt][2], sacc[nt][3]));
        }
        rmax0 = fmaxf(rmax0, __shfl_xor_sync(0xffffffffu, rmax0, 1));
        rmax0 = fmaxf(rmax0, __shfl_xor_sync(0xffffffffu, rmax0, 2));
        rmax1 = fmaxf(rmax1, __shfl_xor_sync(0xffffffffu, rmax1, 1));
        rmax1 = fmaxf(rmax1, __shfl_xor_sync(0xffffffffu, rmax1, 2));
        float newm0 = fmaxf(m0s, rmax0), newm1 = fmaxf(m1s, rmax1);
        float fac0 = __expf(m0s - newm0), fac1 = __expf(m1s - newm1);
        m0s = newm0; m1s = newm1;

        // exp + pack P directly into A-fragment registers
        unsigned pf[4][4];
        float rs0 = 0.0f, rs1 = 0.0f;
#pragma unroll
        for (int nt = 0; nt < 8; nt++) {
            float p0 = __expf(sacc[nt][0] - newm0);
            float p1 = __expf(sacc[nt][1] - newm0);
            float p2 = __expf(sacc[nt][2] - newm1);
            float p3 = __expf(sacc[nt][3] - newm1);
            rs0 += p0 + p1; rs1 += p2 + p3;
            int kk = nt >> 1;
            if ((nt & 1) == 0) {
                pf[kk][0] = pk2(p0, p1);   // row g,   cols kk*16+2t..+1
                pf[kk][1] = pk2(p2, p3);   // row g+8
            } else {
                pf[kk][2] = pk2(p0, p1);   // row g,   cols kk*16+8+2t..+1
                pf[kk][3] = pk2(p2, p3);   // row g+8
            }
        }
        rs0 += __shfl_xor_sync(0xffffffffu, rs0, 1);
        rs0 += __shfl_xor_sync(0xffffffffu, rs0, 2);
        rs1 += __shfl_xor_sync(0xffffffffu, rs1, 1);
        rs1 += __shfl_xor_sync(0xffffffffu, rs1, 2);
        l0s = l0s * fac0 + rs0;
        l1s = l1s * fac1 + rs1;
#pragma unroll
        for (int nt = 0; nt < 16; nt++) {
            oacc[nt][0] *= fac0; oacc[nt][1] *= fac0;
            oacc[nt][2] *= fac1; oacc[nt][3] *= fac1;
        }

        // O += P V  (P from registers; V^T frags via ldmatrix.trans)
#pragma unroll
        for (int kk = 0; kk < 4; kk++) {
#pragma unroll
            for (int np = 0; np < 8; np++) {
                unsigned b0, b1, b2, b3;
                ldsm4t(b0, b1, b2, b3, vbase + kk * 16 * 136 * 2 + np * 32);
                mma_f16(oacc[np * 2], pf[kk], b0, b1);
                mma_f16(oacc[np * 2 + 1], pf[kk], b2, b3);
            }
        }
        __syncthreads();
    }

    float inv0 = 1.0f / l0s, inv1 = 1.0f / l1s;
    int r0 = qbase + warp * 16 + g, r1 = r0 + 8;
#pragma unroll
    for (int nt = 0; nt < 16; nt++) {
        int d = hh * HD + nt * 8 + 2 * t;
        if (r0 < S)
            *(unsigned*)(obuf + (size_t)r0 * DIMC + d) =
                pk2(oacc[nt][0] * inv0, oacc[nt][1] * inv0);
        if (r1 < S)
            *(unsigned*)(obuf + (size_t)r1 * DIMC + d) =
                pk2(oacc[nt][2] * inv1, oacc[nt][3] * inv1);
    }
}

// ---------------------------------------------------------------------------
extern "C" void kernel_launch(void* const* d_in, const int* in_sizes, int n_in,
                              void* d_out, int out_size)
{
    const float* x   = (const float*)d_in[0];
    const float* th  = (const float*)d_in[1];
    const float* ck  = (const float*)d_in[2];
    const float* cv  = (const float*)d_in[3];
    const float* wq  = (const float*)d_in[4];
    const float* bq  = (const float*)d_in[5];
    const float* wk  = (const float*)d_in[6];
    const float* bk  = (const float*)d_in[7];
    const float* wv  = (const float*)d_in[8];
    const float* bv  = (const float*)d_in[9];
    const float* wo  = (const float*)d_in[10];
    const float* bo  = (const float*)d_in[11];
    const float* gq  = (const float*)d_in[12];
    const float* gk  = (const float*)d_in[13];
    const int* p_gh  = (const int*)d_in[15];
    const int* p_gw  = (const int*)d_in[16];
    const int* p_cs  = (const int*)d_in[17];
    const int* p_ge  = (const int*)d_in[18];
    const int* p_le  = (const int*)d_in[19];
    float* out = (float*)d_out;

    int S = in_sizes[0] / DIMC;

    float *qp, *kp;
    __half *xhp, *ohp, *whp, *qhp;
    cudaGetSymbolAddress((void**)&qp, g_q);
    cudaGetSymbolAddress((void**)&kp, g_k);
    cudaGetSymbolAddress((void**)&xhp, g_xh);
    cudaGetSymbolAddress((void**)&ohp, g_oh);
    cudaGetSymbolAddress((void**)&whp, g_wh);
    cudaGetSymbolAddress((void**)&qhp, g_qh);

    int wn8 = DIMC * DIMC / 8;
    prep_half_kernel<<<(4 * wn8 + 255) / 256, 256>>>(wq, wk, wv, wo, whp, wn8);
    int xn8 = S * DIMC / 8;
    prep_half_kernel<<<(xn8 + 255) / 256, 256>>>(x, 0, 0, 0, xhp, xn8);

    size_t gsm = 30720;
    cudaFuncSetAttribute(gemm_f16_kernel, cudaFuncAttributeMaxDynamicSharedMemorySize,
                         (int)gsm);
    dim3 gqkv((S + 63) / 64, DIMC / 128, 3);
    gemm_f16_kernel<<<gqkv, 128, gsm>>>(xhp, whp, bq, bk, bv, qp, kp, S, 1,
                                        p_cs, p_ge, p_le);

    norm_rope_kernel<<<dim3(S, 2), 256>>>(qp, kp, qhp, gq, gk, th, S,
                                          p_gh, p_gw, p_cs, p_ge, p_le);

    prep_kv_kernel<<<dim3(PADW / 64, NHEADS), 256>>>(ck, cv, S, p_cs, p_ge, p_le);

    size_t fsm = (size_t)(2 * 17408) * sizeof(__half);  // 69632 B
    cudaFuncSetAttribute(flash_f16_kernel, cudaFuncAttributeMaxDynamicSharedMemorySize,
                         (int)fsm);
    flash_f16_kernel<<<dim3((S + 63) / 64, NHEADS), 128, fsm>>>(
        qhp, ohp, S, p_cs, p_ge, p_le);

    dim3 go((S + 63) / 64, DIMC / 128, 1);
    gemm_f16_kernel<<<go, 128, gsm>>>(ohp, whp + (size_t)3 * DIMC * DIMC,
                                      bo, bo, bo, out, out, S, 0,
                                      p_cs, p_ge, p_le);
}